// round 1
// baseline (speedup 1.0000x reference)
#include <cuda_runtime.h>
#include <cuda_bf16.h>

// Problem constants (fixed by the dataset)
constexpr int NN = 100000;   // nodes
constexpr int EE = 1600000;  // edges
constexpr int DD = 64;       // feature dim
constexpr int GG = 512;      // graphs
constexpr int CC = 10;       // classes
constexpr int LL = 5;        // layers (4 conv layers)
constexpr float BN_EPS = 1e-5f;

// Scratch (device globals; no allocation allowed)
__device__ float g_h[NN * DD];
__device__ float g_z[NN * DD];
__device__ float g_t[NN * DD];
__device__ float g_u[NN * DD];
__device__ float g_pooled[LL * GG * DD];
__device__ float g_stats[8 * 128];  // per BN: [0..63]=colsum, [64..127]=colsumsq
__device__ float g_ab[8 * 128];     // per BN: [0..63]=alpha, [64..127]=beta

// ---------------------------------------------------------------------------
// helpers
// ---------------------------------------------------------------------------
__device__ __forceinline__ void red4(float* p, float4 v) {
    asm volatile("red.global.add.v4.f32 [%0], {%1,%2,%3,%4};"
                 :: "l"(p), "f"(v.x), "f"(v.y), "f"(v.z), "f"(v.w) : "memory");
}

__device__ __forceinline__ float2 f2fma(float2 a, float2 b, float2 c) {
    float2 d;
    asm("{\n\t"
        ".reg .b64 ra, rb, rc, rd;\n\t"
        "mov.b64 ra, {%2, %3};\n\t"
        "mov.b64 rb, {%4, %5};\n\t"
        "mov.b64 rc, {%6, %7};\n\t"
        "fma.rn.f32x2 rd, ra, rb, rc;\n\t"
        "mov.b64 {%0, %1}, rd;\n\t"
        "}"
        : "=f"(d.x), "=f"(d.y)
        : "f"(a.x), "f"(a.y), "f"(b.x), "f"(b.y), "f"(c.x), "f"(c.y));
    return d;
}

// ---------------------------------------------------------------------------
// zero accumulators
// ---------------------------------------------------------------------------
__global__ void zerok(float* __restrict__ pooled, float* __restrict__ stats) {
    int i = blockIdx.x * 256 + threadIdx.x;
    if (i < LL * GG * DD) pooled[i] = 0.f;
    if (i < 8 * 128) stats[i] = 0.f;
}

// ---------------------------------------------------------------------------
// h-epilogue: h = relu(bn(src)) (or passthrough), pool into pooled_l,
// optionally pre-init z = (1+eps_next)*h for the next layer's scatter.
// One thread per float4 of one row.
// ---------------------------------------------------------------------------
__global__ void __launch_bounds__(256) hpool_kernel(
    const float* __restrict__ src, const float* __restrict__ ab,
    const int* __restrict__ batch, const float* __restrict__ eps_next,
    float* __restrict__ h, float* __restrict__ z, float* __restrict__ pooled_l,
    int nrows)
{
    int idx = blockIdx.x * 256 + threadIdx.x;
    int n = idx >> 4;
    int j = (idx & 15) << 2;
    if (n >= nrows) return;
    float4 v = *(const float4*)(src + n * DD + j);
    if (ab) {
        v.x = fmaxf(fmaf(ab[j + 0], v.x, ab[64 + j + 0]), 0.f);
        v.y = fmaxf(fmaf(ab[j + 1], v.y, ab[64 + j + 1]), 0.f);
        v.z = fmaxf(fmaf(ab[j + 2], v.z, ab[64 + j + 2]), 0.f);
        v.w = fmaxf(fmaf(ab[j + 3], v.w, ab[64 + j + 3]), 0.f);
    }
    *(float4*)(h + n * DD + j) = v;
    if (z) {
        float e = 1.0f + *eps_next;
        float4 zz = make_float4(v.x * e, v.y * e, v.z * e, v.w * e);
        *(float4*)(z + n * DD + j) = zz;
    }
    int g = batch[n];
    red4(pooled_l + g * DD + j, v);
}

// ---------------------------------------------------------------------------
// edge scatter: z[dst] += h[src]   (one thread per (edge, float4-chunk))
// ---------------------------------------------------------------------------
__global__ void __launch_bounds__(256) scatter_kernel(
    const float* __restrict__ h, const int* __restrict__ ei,
    float* __restrict__ z, int nedges)
{
    int idx = blockIdx.x * 256 + threadIdx.x;
    int e = idx >> 4;
    int j = (idx & 15) << 2;
    if (e >= nedges) return;
    int s = ei[e];
    int d = ei[nedges + e];
    float4 v = *(const float4*)(h + s * DD + j);
    red4(z + d * DD + j, v);
}

// ---------------------------------------------------------------------------
// GEMM: Out[N,64] = transform(A)[N,64] @ W[64,64] + bias
// transform(a)[.,k] = relu(alpha[k]*a + beta[k]) if ab != null, else identity.
// Block: 256 threads, 64 rows. Thread: 2 rows x 8 cols (cols {4tc..}, {32+4tc..}).
// Packed f32x2 FMAs; smem padded to avoid bank conflicts.
// ---------------------------------------------------------------------------
__global__ void __launch_bounds__(256) gemm64(
    const float* __restrict__ A, const float* __restrict__ W,
    const float* __restrict__ bias, const float* __restrict__ ab,
    float* __restrict__ Out, int nrows)
{
    __shared__ float Ws[64][68];
    __shared__ float As[64][68];
    const int tid = threadIdx.x;
    const int row0 = blockIdx.x * 64;

    // load W (64x64) into smem
    for (int i = tid; i < 1024; i += 256) {
        int k = i >> 4, c = (i & 15) << 2;
        float4 w = *(const float4*)(W + k * 64 + c);
        *(float4*)&Ws[k][c] = w;
    }
    // load A tile with optional BN+ReLU transform
    for (int i = tid; i < 1024; i += 256) {
        int r = i >> 4, c = (i & 15) << 2;
        int gr = row0 + r;
        float4 a = make_float4(0.f, 0.f, 0.f, 0.f);
        if (gr < nrows) a = *(const float4*)(A + gr * 64 + c);
        if (ab) {
            a.x = fmaxf(fmaf(ab[c + 0], a.x, ab[64 + c + 0]), 0.f);
            a.y = fmaxf(fmaf(ab[c + 1], a.y, ab[64 + c + 1]), 0.f);
            a.z = fmaxf(fmaf(ab[c + 2], a.z, ab[64 + c + 2]), 0.f);
            a.w = fmaxf(fmaf(ab[c + 3], a.w, ab[64 + c + 3]), 0.f);
        }
        *(float4*)&As[r][c] = a;
    }
    __syncthreads();

    const int tc = tid & 7;     // col group
    const int rg = tid >> 3;    // 0..31
    const int r0 = 2 * rg;

    float2 acc[2][4];
#pragma unroll
    for (int i = 0; i < 2; i++)
#pragma unroll
        for (int jq = 0; jq < 4; jq++) acc[i][jq] = make_float2(0.f, 0.f);

#pragma unroll
    for (int kc = 0; kc < 64; kc += 16) {
        float a0[16], a1[16];
#pragma unroll
        for (int q = 0; q < 4; q++) {
            float4 t0 = *(const float4*)&As[r0][kc + 4 * q];
            a0[4 * q + 0] = t0.x; a0[4 * q + 1] = t0.y; a0[4 * q + 2] = t0.z; a0[4 * q + 3] = t0.w;
            float4 t1 = *(const float4*)&As[r0 + 1][kc + 4 * q];
            a1[4 * q + 0] = t1.x; a1[4 * q + 1] = t1.y; a1[4 * q + 2] = t1.z; a1[4 * q + 3] = t1.w;
        }
#pragma unroll
        for (int kk = 0; kk < 16; kk++) {
            const float* wr = &Ws[kc + kk][4 * tc];
            float4 wl = *(const float4*)wr;
            float4 wh = *(const float4*)(wr + 32);
            float2 wl01 = make_float2(wl.x, wl.y), wl23 = make_float2(wl.z, wl.w);
            float2 wh01 = make_float2(wh.x, wh.y), wh23 = make_float2(wh.z, wh.w);
            float2 A0 = make_float2(a0[kk], a0[kk]);
            float2 A1 = make_float2(a1[kk], a1[kk]);
            acc[0][0] = f2fma(A0, wl01, acc[0][0]);
            acc[0][1] = f2fma(A0, wl23, acc[0][1]);
            acc[0][2] = f2fma(A0, wh01, acc[0][2]);
            acc[0][3] = f2fma(A0, wh23, acc[0][3]);
            acc[1][0] = f2fma(A1, wl01, acc[1][0]);
            acc[1][1] = f2fma(A1, wl23, acc[1][1]);
            acc[1][2] = f2fma(A1, wh01, acc[1][2]);
            acc[1][3] = f2fma(A1, wh23, acc[1][3]);
        }
    }

    float4 blo = *(const float4*)(bias + 4 * tc);
    float4 bhi = *(const float4*)(bias + 32 + 4 * tc);
#pragma unroll
    for (int i = 0; i < 2; i++) {
        int gr = row0 + r0 + i;
        if (gr < nrows) {
            float4 o0 = make_float4(acc[i][0].x + blo.x, acc[i][0].y + blo.y,
                                    acc[i][1].x + blo.z, acc[i][1].y + blo.w);
            float4 o1 = make_float4(acc[i][2].x + bhi.x, acc[i][2].y + bhi.y,
                                    acc[i][3].x + bhi.z, acc[i][3].y + bhi.w);
            *(float4*)(Out + gr * 64 + 4 * tc) = o0;
            *(float4*)(Out + gr * 64 + 32 + 4 * tc) = o1;
        }
    }
}

// ---------------------------------------------------------------------------
// column stats: st[0..63] += colsum, st[64..127] += colsumsq
// ---------------------------------------------------------------------------
__global__ void __launch_bounds__(256) stats_kernel(
    const float* __restrict__ X, float* __restrict__ st, int nrows)
{
    const int tid = threadIdx.x;
    const int cg = tid & 15;
    const int c = cg << 2;
    int row = (blockIdx.x * 256 + tid) >> 4;
    const int rstride = (gridDim.x * 256) >> 4;

    float4 s = make_float4(0.f, 0.f, 0.f, 0.f);
    float4 q = make_float4(0.f, 0.f, 0.f, 0.f);
    for (; row < nrows; row += rstride) {
        float4 v = *(const float4*)(X + row * DD + c);
        s.x += v.x; s.y += v.y; s.z += v.z; s.w += v.w;
        q.x += v.x * v.x; q.y += v.y * v.y; q.z += v.z * v.z; q.w += v.w * v.w;
    }
    // lanes l and l+16 share the same column group
    s.x += __shfl_xor_sync(0xffffffffu, s.x, 16);
    s.y += __shfl_xor_sync(0xffffffffu, s.y, 16);
    s.z += __shfl_xor_sync(0xffffffffu, s.z, 16);
    s.w += __shfl_xor_sync(0xffffffffu, s.w, 16);
    q.x += __shfl_xor_sync(0xffffffffu, q.x, 16);
    q.y += __shfl_xor_sync(0xffffffffu, q.y, 16);
    q.z += __shfl_xor_sync(0xffffffffu, q.z, 16);
    q.w += __shfl_xor_sync(0xffffffffu, q.w, 16);

    __shared__ float sm[128];
    if (tid < 128) sm[tid] = 0.f;
    __syncthreads();
    if ((tid & 31) < 16) {
        atomicAdd(&sm[c + 0], s.x); atomicAdd(&sm[c + 1], s.y);
        atomicAdd(&sm[c + 2], s.z); atomicAdd(&sm[c + 3], s.w);
        atomicAdd(&sm[64 + c + 0], q.x); atomicAdd(&sm[64 + c + 1], q.y);
        atomicAdd(&sm[64 + c + 2], q.z); atomicAdd(&sm[64 + c + 3], q.w);
    }
    __syncthreads();
    if (tid < 128) atomicAdd(&st[tid], sm[tid]);
}

// ---------------------------------------------------------------------------
// BN finalize: alpha = gamma*rstd ; beta = shift - alpha*mean
// ---------------------------------------------------------------------------
__global__ void bnfin_kernel(const float* __restrict__ st,
                             const float* __restrict__ gamma,
                             const float* __restrict__ beta,
                             float* __restrict__ ab)
{
    int c = threadIdx.x;
    const float inv_n = 1.0f / (float)NN;
    float m = st[c] * inv_n;
    float v = st[64 + c] * inv_n - m * m;
    float rs = rsqrtf(v + BN_EPS);
    float al = gamma[c] * rs;
    ab[c] = al;
    ab[64 + c] = beta[c] - al * m;
}

// ---------------------------------------------------------------------------
// final readout: score[g,c] = sum_l ( pooled[l,g,:] @ Wp[l,:,c] + bp[l,c] )
// ---------------------------------------------------------------------------
__global__ void score_kernel(const float* __restrict__ pooled,
                             const float* __restrict__ Wp,
                             const float* __restrict__ bp,
                             float* __restrict__ out)
{
    int t = blockIdx.x * 256 + threadIdx.x;
    if (t >= GG * CC) return;
    int g = t / CC, c = t % CC;
    float acc = 0.f;
#pragma unroll
    for (int l = 0; l < LL; l++) {
        acc += bp[l * CC + c];
        const float* pl = pooled + (l * GG + g) * DD;
        const float* wl = Wp + l * DD * CC + c;
        float s = 0.f;
#pragma unroll
        for (int d = 0; d < DD; d++) s += pl[d] * wl[d * CC];
        acc += s;
    }
    out[g * CC + c] = acc;
}

// ---------------------------------------------------------------------------
extern "C" void kernel_launch(void* const* d_in, const int* in_sizes, int n_in,
                              void* d_out, int out_size)
{
    (void)in_sizes; (void)n_in; (void)out_size;
    const float* x     = (const float*)d_in[0];
    const int*   ei    = (const int*)d_in[1];
    const int*   batch = (const int*)d_in[2];
    const float* eps   = (const float*)d_in[3];
    const float* W1    = (const float*)d_in[4];
    const float* b1    = (const float*)d_in[5];
    const float* g1    = (const float*)d_in[6];
    const float* be1   = (const float*)d_in[7];
    const float* W2    = (const float*)d_in[8];
    const float* b2    = (const float*)d_in[9];
    const float* gout  = (const float*)d_in[10];
    const float* beout = (const float*)d_in[11];
    const float* Wp    = (const float*)d_in[12];
    const float* bp    = (const float*)d_in[13];

    float *h, *z, *t, *u, *pooled, *stats, *ab;
    cudaGetSymbolAddress((void**)&h, g_h);
    cudaGetSymbolAddress((void**)&z, g_z);
    cudaGetSymbolAddress((void**)&t, g_t);
    cudaGetSymbolAddress((void**)&u, g_u);
    cudaGetSymbolAddress((void**)&pooled, g_pooled);
    cudaGetSymbolAddress((void**)&stats, g_stats);
    cudaGetSymbolAddress((void**)&ab, g_ab);

    const int HPB = (NN * 16) / 256;          // 6250
    const int SCB = (EE * 16) / 256;          // 100000
    const int GMB = (NN + 63) / 64;           // 1563
    const int STB = 1184;

    zerok<<<(LL * GG * DD + 255) / 256, 256>>>(pooled, stats);

    // layer 0 input: h = x, z = (1+eps[0])*x, pool hidden_rep[0]
    hpool_kernel<<<HPB, 256>>>(x, nullptr, batch, eps, h, z, pooled, NN);

    for (int l = 0; l < LL - 1; l++) {
        scatter_kernel<<<SCB, 256>>>(h, ei, z, EE);
        gemm64<<<GMB, 256>>>(z, W1 + l * 4096, b1 + l * 64, nullptr, t, NN);
        stats_kernel<<<STB, 256>>>(t, stats + (2 * l) * 128, NN);
        bnfin_kernel<<<1, 64>>>(stats + (2 * l) * 128, g1 + l * 64, be1 + l * 64,
                                ab + (2 * l) * 128);
        gemm64<<<GMB, 256>>>(t, W2 + l * 4096, b2 + l * 64, ab + (2 * l) * 128, u, NN);
        stats_kernel<<<STB, 256>>>(u, stats + (2 * l + 1) * 128, NN);
        bnfin_kernel<<<1, 64>>>(stats + (2 * l + 1) * 128, gout + l * 64, beout + l * 64,
                                ab + (2 * l + 1) * 128);
        hpool_kernel<<<HPB, 256>>>(u, ab + (2 * l + 1) * 128, batch,
                                   (l < LL - 2) ? (eps + l + 1) : nullptr,
                                   h, (l < LL - 2) ? z : nullptr,
                                   pooled + (l + 1) * GG * DD, NN);
    }

    score_kernel<<<(GG * CC + 255) / 256, 256>>>(pooled, Wp, bp, (float*)d_out);
}

// round 2
// speedup vs baseline: 1.4395x; 1.4395x over previous
#include <cuda_runtime.h>
#include <cuda_bf16.h>

// Problem constants (fixed by the dataset)
constexpr int NN = 100000;   // nodes
constexpr int EE = 1600000;  // edges
constexpr int DD = 64;       // feature dim
constexpr int GG = 512;      // graphs
constexpr int CC = 10;       // classes
constexpr int LL = 5;        // layers (4 conv layers)
constexpr float BN_EPS = 1e-5f;
constexpr int SCAN_B = 1024;
constexpr int NBLK = (NN + SCAN_B - 1) / SCAN_B;   // 98

// Scratch (device globals; no allocation allowed)
__device__ float g_h[NN * DD];
__device__ float g_z[NN * DD];
__device__ float g_t[NN * DD];
__device__ float g_u[NN * DD];
__device__ float g_pooled[LL * GG * DD];
__device__ float g_stats[8 * 128];  // per BN: [0..63]=colsum, [64..127]=colsumsq
__device__ float g_ab[8 * 128];     // per BN: [0..63]=alpha, [64..127]=beta
__device__ int   g_rowptr[NN + 1];
__device__ int   g_cursor[NN];
__device__ int   g_csr[EE];
__device__ int   g_bsum[NBLK];

// ---------------------------------------------------------------------------
// helpers
// ---------------------------------------------------------------------------
__device__ __forceinline__ void red4(float* p, float4 v) {
    asm volatile("red.global.add.v4.f32 [%0], {%1,%2,%3,%4};"
                 :: "l"(p), "f"(v.x), "f"(v.y), "f"(v.z), "f"(v.w) : "memory");
}

__device__ __forceinline__ float2 f2fma(float2 a, float2 b, float2 c) {
    float2 d;
    asm("{\n\t"
        ".reg .b64 ra, rb, rc, rd;\n\t"
        "mov.b64 ra, {%2, %3};\n\t"
        "mov.b64 rb, {%4, %5};\n\t"
        "mov.b64 rc, {%6, %7};\n\t"
        "fma.rn.f32x2 rd, ra, rb, rc;\n\t"
        "mov.b64 {%0, %1}, rd;\n\t"
        "}"
        : "=f"(d.x), "=f"(d.y)
        : "f"(a.x), "f"(a.y), "f"(b.x), "f"(b.y), "f"(c.x), "f"(c.y));
    return d;
}

// ---------------------------------------------------------------------------
// zero accumulators + degree counters (reuse g_rowptr as count buffer)
// ---------------------------------------------------------------------------
__global__ void zerok(float* __restrict__ pooled, float* __restrict__ stats,
                      int* __restrict__ cnt) {
    int i = blockIdx.x * 256 + threadIdx.x;
    if (i < LL * GG * DD) pooled[i] = 0.f;
    if (i < 8 * 128) stats[i] = 0.f;
    if (i <= NN) cnt[i] = 0;
}

// ---------------------------------------------------------------------------
// CSR build: histogram of dst degrees
// ---------------------------------------------------------------------------
__global__ void __launch_bounds__(256) hist_kernel(const int* __restrict__ ei,
                                                   int* __restrict__ cnt) {
    int e = blockIdx.x * 256 + threadIdx.x;
    if (e < EE) atomicAdd(&cnt[ei[EE + e]], 1);
}

// block-level exclusive scan (in-place convert cnt -> rowptr partials)
__global__ void __launch_bounds__(SCAN_B) scanA_kernel(int* __restrict__ rp,
                                                       int* __restrict__ bsum) {
    __shared__ int sm[SCAN_B];
    int gid = blockIdx.x * SCAN_B + threadIdx.x;
    int v = (gid < NN) ? rp[gid] : 0;
    sm[threadIdx.x] = v;
    __syncthreads();
    for (int off = 1; off < SCAN_B; off <<= 1) {
        int t = (threadIdx.x >= off) ? sm[threadIdx.x - off] : 0;
        __syncthreads();
        sm[threadIdx.x] += t;
        __syncthreads();
    }
    if (gid < NN) rp[gid] = sm[threadIdx.x] - v;   // exclusive
    if (threadIdx.x == SCAN_B - 1) bsum[blockIdx.x] = sm[SCAN_B - 1];
}

__global__ void scanB_kernel(int* __restrict__ bsum) {
    if (threadIdx.x == 0) {
        int acc = 0;
        for (int i = 0; i < NBLK; i++) { int t = bsum[i]; bsum[i] = acc; acc += t; }
    }
}

__global__ void __launch_bounds__(SCAN_B) scanC_kernel(int* __restrict__ rp,
                                                       const int* __restrict__ bsum,
                                                       int* __restrict__ cursor) {
    int gid = blockIdx.x * SCAN_B + threadIdx.x;
    if (gid < NN) {
        int v = rp[gid] + bsum[blockIdx.x];
        rp[gid] = v;
        cursor[gid] = v;
    }
    if (gid == 0) rp[NN] = EE;
}

__global__ void __launch_bounds__(256) fill_kernel(const int* __restrict__ ei,
                                                   int* __restrict__ cursor,
                                                   int* __restrict__ csr) {
    int e = blockIdx.x * 256 + threadIdx.x;
    if (e < EE) {
        int d = ei[EE + e];
        int pos = atomicAdd(&cursor[d], 1);
        csr[pos] = ei[e];
    }
}

// ---------------------------------------------------------------------------
// gather aggregation: z[n] = (1+eps)*h[n] + sum_{nbr} h[nbr]
// 16 threads per node, thread handles one float4 column chunk.
// ---------------------------------------------------------------------------
__global__ void __launch_bounds__(256) gather_kernel(
    const float* __restrict__ h, const int* __restrict__ rowptr,
    const int* __restrict__ csr, const float* __restrict__ eps_l,
    float* __restrict__ z)
{
    int idx = blockIdx.x * 256 + threadIdx.x;
    int n = idx >> 4;
    int j = (idx & 15) << 2;
    if (n >= NN) return;
    int s = rowptr[n];
    int e = rowptr[n + 1];
    float em1 = 1.0f + *eps_l;
    float4 hv = *(const float4*)(h + n * DD + j);
    float4 acc = make_float4(em1 * hv.x, em1 * hv.y, em1 * hv.z, em1 * hv.w);
    int i = s;
    for (; i + 4 <= e; i += 4) {
        int s0 = csr[i], s1 = csr[i + 1], s2 = csr[i + 2], s3 = csr[i + 3];
        float4 v0 = *(const float4*)(h + s0 * DD + j);
        float4 v1 = *(const float4*)(h + s1 * DD + j);
        float4 v2 = *(const float4*)(h + s2 * DD + j);
        float4 v3 = *(const float4*)(h + s3 * DD + j);
        acc.x += v0.x + v1.x + v2.x + v3.x;
        acc.y += v0.y + v1.y + v2.y + v3.y;
        acc.z += v0.z + v1.z + v2.z + v3.z;
        acc.w += v0.w + v1.w + v2.w + v3.w;
    }
    for (; i < e; i++) {
        int sv = csr[i];
        float4 v = *(const float4*)(h + sv * DD + j);
        acc.x += v.x; acc.y += v.y; acc.z += v.z; acc.w += v.w;
    }
    *(float4*)(z + n * DD + j) = acc;
}

// ---------------------------------------------------------------------------
// h-epilogue: h = relu(bn(src)) (or passthrough), pool into pooled_l
// ---------------------------------------------------------------------------
__global__ void __launch_bounds__(256) hpool_kernel(
    const float* __restrict__ src, const float* __restrict__ ab,
    const int* __restrict__ batch,
    float* __restrict__ h, float* __restrict__ pooled_l, int nrows)
{
    int idx = blockIdx.x * 256 + threadIdx.x;
    int n = idx >> 4;
    int j = (idx & 15) << 2;
    if (n >= nrows) return;
    float4 v = *(const float4*)(src + n * DD + j);
    if (ab) {
        v.x = fmaxf(fmaf(ab[j + 0], v.x, ab[64 + j + 0]), 0.f);
        v.y = fmaxf(fmaf(ab[j + 1], v.y, ab[64 + j + 1]), 0.f);
        v.z = fmaxf(fmaf(ab[j + 2], v.z, ab[64 + j + 2]), 0.f);
        v.w = fmaxf(fmaf(ab[j + 3], v.w, ab[64 + j + 3]), 0.f);
    }
    *(float4*)(h + n * DD + j) = v;
    int g = batch[n];
    red4(pooled_l + g * DD + j, v);
}

// ---------------------------------------------------------------------------
// GEMM: Out[N,64] = transform(A)[N,64] @ W[64,64] + bias, fused column stats.
// transform(a)[.,k] = relu(alpha[k]*a + beta[k]) if ab != null, else identity.
// Block: 256 threads, 64 rows. Thread: 2 rows x 8 cols.
// ---------------------------------------------------------------------------
__global__ void __launch_bounds__(256) gemm64(
    const float* __restrict__ A, const float* __restrict__ W,
    const float* __restrict__ bias, const float* __restrict__ ab,
    float* __restrict__ Out, float* __restrict__ st, int nrows)
{
    __shared__ float Ws[64][68];
    __shared__ float As[64][68];
    __shared__ float sst[128];
    const int tid = threadIdx.x;
    const int row0 = blockIdx.x * 64;

    if (tid < 128) sst[tid] = 0.f;

    // load W (64x64) into smem
    for (int i = tid; i < 1024; i += 256) {
        int k = i >> 4, c = (i & 15) << 2;
        float4 w = *(const float4*)(W + k * 64 + c);
        *(float4*)&Ws[k][c] = w;
    }
    // load A tile with optional BN+ReLU transform
    for (int i = tid; i < 1024; i += 256) {
        int r = i >> 4, c = (i & 15) << 2;
        int gr = row0 + r;
        float4 a = make_float4(0.f, 0.f, 0.f, 0.f);
        if (gr < nrows) a = *(const float4*)(A + gr * 64 + c);
        if (ab) {
            a.x = fmaxf(fmaf(ab[c + 0], a.x, ab[64 + c + 0]), 0.f);
            a.y = fmaxf(fmaf(ab[c + 1], a.y, ab[64 + c + 1]), 0.f);
            a.z = fmaxf(fmaf(ab[c + 2], a.z, ab[64 + c + 2]), 0.f);
            a.w = fmaxf(fmaf(ab[c + 3], a.w, ab[64 + c + 3]), 0.f);
        }
        *(float4*)&As[r][c] = a;
    }
    __syncthreads();

    const int tc = tid & 7;     // col group
    const int rg = tid >> 3;    // 0..31
    const int r0 = 2 * rg;

    float2 acc[2][4];
#pragma unroll
    for (int i = 0; i < 2; i++)
#pragma unroll
        for (int jq = 0; jq < 4; jq++) acc[i][jq] = make_float2(0.f, 0.f);

#pragma unroll
    for (int kc = 0; kc < 64; kc += 16) {
        float a0[16], a1[16];
#pragma unroll
        for (int q = 0; q < 4; q++) {
            float4 t0 = *(const float4*)&As[r0][kc + 4 * q];
            a0[4 * q + 0] = t0.x; a0[4 * q + 1] = t0.y; a0[4 * q + 2] = t0.z; a0[4 * q + 3] = t0.w;
            float4 t1 = *(const float4*)&As[r0 + 1][kc + 4 * q];
            a1[4 * q + 0] = t1.x; a1[4 * q + 1] = t1.y; a1[4 * q + 2] = t1.z; a1[4 * q + 3] = t1.w;
        }
#pragma unroll
        for (int kk = 0; kk < 16; kk++) {
            const float* wr = &Ws[kc + kk][4 * tc];
            float4 wl = *(const float4*)wr;
            float4 wh = *(const float4*)(wr + 32);
            float2 wl01 = make_float2(wl.x, wl.y), wl23 = make_float2(wl.z, wl.w);
            float2 wh01 = make_float2(wh.x, wh.y), wh23 = make_float2(wh.z, wh.w);
            float2 A0 = make_float2(a0[kk], a0[kk]);
            float2 A1 = make_float2(a1[kk], a1[kk]);
            acc[0][0] = f2fma(A0, wl01, acc[0][0]);
            acc[0][1] = f2fma(A0, wl23, acc[0][1]);
            acc[0][2] = f2fma(A0, wh01, acc[0][2]);
            acc[0][3] = f2fma(A0, wh23, acc[0][3]);
            acc[1][0] = f2fma(A1, wl01, acc[1][0]);
            acc[1][1] = f2fma(A1, wl23, acc[1][1]);
            acc[1][2] = f2fma(A1, wh01, acc[1][2]);
            acc[1][3] = f2fma(A1, wh23, acc[1][3]);
        }
    }

    float4 blo = *(const float4*)(bias + 4 * tc);
    float4 bhi = *(const float4*)(bias + 32 + 4 * tc);
    float4 slo = make_float4(0.f, 0.f, 0.f, 0.f), shi = slo, qlo = slo, qhi = slo;
#pragma unroll
    for (int i = 0; i < 2; i++) {
        int gr = row0 + r0 + i;
        if (gr < nrows) {
            float4 o0 = make_float4(acc[i][0].x + blo.x, acc[i][0].y + blo.y,
                                    acc[i][1].x + blo.z, acc[i][1].y + blo.w);
            float4 o1 = make_float4(acc[i][2].x + bhi.x, acc[i][2].y + bhi.y,
                                    acc[i][3].x + bhi.z, acc[i][3].y + bhi.w);
            *(float4*)(Out + gr * 64 + 4 * tc) = o0;
            *(float4*)(Out + gr * 64 + 32 + 4 * tc) = o1;
            slo.x += o0.x; slo.y += o0.y; slo.z += o0.z; slo.w += o0.w;
            shi.x += o1.x; shi.y += o1.y; shi.z += o1.z; shi.w += o1.w;
            qlo.x += o0.x * o0.x; qlo.y += o0.y * o0.y; qlo.z += o0.z * o0.z; qlo.w += o0.w * o0.w;
            qhi.x += o1.x * o1.x; qhi.y += o1.y * o1.y; qhi.z += o1.z * o1.z; qhi.w += o1.w * o1.w;
        }
    }
    // reduce across the 4 lanes in this warp that share tc (lanes differ in bits 3,4)
#pragma unroll
    for (int m = 8; m <= 16; m <<= 1) {
        slo.x += __shfl_xor_sync(~0u, slo.x, m); slo.y += __shfl_xor_sync(~0u, slo.y, m);
        slo.z += __shfl_xor_sync(~0u, slo.z, m); slo.w += __shfl_xor_sync(~0u, slo.w, m);
        shi.x += __shfl_xor_sync(~0u, shi.x, m); shi.y += __shfl_xor_sync(~0u, shi.y, m);
        shi.z += __shfl_xor_sync(~0u, shi.z, m); shi.w += __shfl_xor_sync(~0u, shi.w, m);
        qlo.x += __shfl_xor_sync(~0u, qlo.x, m); qlo.y += __shfl_xor_sync(~0u, qlo.y, m);
        qlo.z += __shfl_xor_sync(~0u, qlo.z, m); qlo.w += __shfl_xor_sync(~0u, qlo.w, m);
        qhi.x += __shfl_xor_sync(~0u, qhi.x, m); qhi.y += __shfl_xor_sync(~0u, qhi.y, m);
        qhi.z += __shfl_xor_sync(~0u, qhi.z, m); qhi.w += __shfl_xor_sync(~0u, qhi.w, m);
    }
    if ((tid & 24) == 0) {   // lanes 0..7 of each warp
        int c = 4 * tc;
        atomicAdd(&sst[c + 0], slo.x); atomicAdd(&sst[c + 1], slo.y);
        atomicAdd(&sst[c + 2], slo.z); atomicAdd(&sst[c + 3], slo.w);
        atomicAdd(&sst[32 + c + 0], shi.x); atomicAdd(&sst[32 + c + 1], shi.y);
        atomicAdd(&sst[32 + c + 2], shi.z); atomicAdd(&sst[32 + c + 3], shi.w);
        atomicAdd(&sst[64 + c + 0], qlo.x); atomicAdd(&sst[64 + c + 1], qlo.y);
        atomicAdd(&sst[64 + c + 2], qlo.z); atomicAdd(&sst[64 + c + 3], qlo.w);
        atomicAdd(&sst[96 + c + 0], qhi.x); atomicAdd(&sst[96 + c + 1], qhi.y);
        atomicAdd(&sst[96 + c + 2], qhi.z); atomicAdd(&sst[96 + c + 3], qhi.w);
    }
    __syncthreads();
    if (tid < 128) atomicAdd(&st[tid], sst[tid]);
}

// ---------------------------------------------------------------------------
// BN finalize: alpha = gamma*rstd ; beta = shift - alpha*mean
// stats layout from gemm: [0..31]=sum lo cols, [32..63]=sum hi cols,
// [64..95]=sq lo, [96..127]=sq hi  -> column c sum at (c<32 ? c : 32+c-32) = c,
// actually lo cols are 0..31? lo cols are 4tc..4tc+3 for tc 0..7 = cols 0..31. hi = 32..63.
// so sum[c] = st[c], sq[c] = st[64 + c]. Same as before.
// ---------------------------------------------------------------------------
__global__ void bnfin_kernel(const float* __restrict__ st,
                             const float* __restrict__ gamma,
                             const float* __restrict__ beta,
                             float* __restrict__ ab)
{
    int c = threadIdx.x;
    const float inv_n = 1.0f / (float)NN;
    float m = st[c] * inv_n;
    float v = st[64 + c] * inv_n - m * m;
    float rs = rsqrtf(v + BN_EPS);
    float al = gamma[c] * rs;
    ab[c] = al;
    ab[64 + c] = beta[c] - al * m;
}

// ---------------------------------------------------------------------------
// final readout: score[g,c] = sum_l ( pooled[l,g,:] @ Wp[l,:,c] + bp[l,c] )
// ---------------------------------------------------------------------------
__global__ void score_kernel(const float* __restrict__ pooled,
                             const float* __restrict__ Wp,
                             const float* __restrict__ bp,
                             float* __restrict__ out)
{
    int t = blockIdx.x * 256 + threadIdx.x;
    if (t >= GG * CC) return;
    int g = t / CC, c = t % CC;
    float acc = 0.f;
#pragma unroll
    for (int l = 0; l < LL; l++) {
        acc += bp[l * CC + c];
        const float* pl = pooled + (l * GG + g) * DD;
        const float* wl = Wp + l * DD * CC + c;
        float s = 0.f;
#pragma unroll
        for (int d = 0; d < DD; d++) s += pl[d] * wl[d * CC];
        acc += s;
    }
    out[g * CC + c] = acc;
}

// ---------------------------------------------------------------------------
extern "C" void kernel_launch(void* const* d_in, const int* in_sizes, int n_in,
                              void* d_out, int out_size)
{
    (void)in_sizes; (void)n_in; (void)out_size;
    const float* x     = (const float*)d_in[0];
    const int*   ei    = (const int*)d_in[1];
    const int*   batch = (const int*)d_in[2];
    const float* eps   = (const float*)d_in[3];
    const float* W1    = (const float*)d_in[4];
    const float* b1    = (const float*)d_in[5];
    const float* g1    = (const float*)d_in[6];
    const float* be1   = (const float*)d_in[7];
    const float* W2    = (const float*)d_in[8];
    const float* b2    = (const float*)d_in[9];
    const float* gout  = (const float*)d_in[10];
    const float* beout = (const float*)d_in[11];
    const float* Wp    = (const float*)d_in[12];
    const float* bp    = (const float*)d_in[13];

    float *h, *z, *t, *u, *pooled, *stats, *ab;
    int *rowptr, *cursor, *csr, *bsum;
    cudaGetSymbolAddress((void**)&h, g_h);
    cudaGetSymbolAddress((void**)&z, g_z);
    cudaGetSymbolAddress((void**)&t, g_t);
    cudaGetSymbolAddress((void**)&u, g_u);
    cudaGetSymbolAddress((void**)&pooled, g_pooled);
    cudaGetSymbolAddress((void**)&stats, g_stats);
    cudaGetSymbolAddress((void**)&ab, g_ab);
    cudaGetSymbolAddress((void**)&rowptr, g_rowptr);
    cudaGetSymbolAddress((void**)&cursor, g_cursor);
    cudaGetSymbolAddress((void**)&csr, g_csr);
    cudaGetSymbolAddress((void**)&bsum, g_bsum);

    const int HPB = (NN * 16) / 256;          // 6250
    const int EB  = (EE + 255) / 256;         // 6250
    const int GMB = (NN + 63) / 64;           // 1563

    zerok<<<(LL * GG * DD + 255) / 256, 256>>>(pooled, stats, rowptr);

    // CSR build
    hist_kernel<<<EB, 256>>>(ei, rowptr);
    scanA_kernel<<<NBLK, SCAN_B>>>(rowptr, bsum);
    scanB_kernel<<<1, 32>>>(bsum);
    scanC_kernel<<<NBLK, SCAN_B>>>(rowptr, bsum, cursor);
    fill_kernel<<<EB, 256>>>(ei, cursor, csr);

    // layer 0 input: h = x, pool hidden_rep[0]
    hpool_kernel<<<HPB, 256>>>(x, nullptr, batch, h, pooled, NN);

    for (int l = 0; l < LL - 1; l++) {
        gather_kernel<<<HPB, 256>>>(h, rowptr, csr, eps + l, z);
        gemm64<<<GMB, 256>>>(z, W1 + l * 4096, b1 + l * 64, nullptr, t,
                             stats + (2 * l) * 128, NN);
        bnfin_kernel<<<1, 64>>>(stats + (2 * l) * 128, g1 + l * 64, be1 + l * 64,
                                ab + (2 * l) * 128);
        gemm64<<<GMB, 256>>>(t, W2 + l * 4096, b2 + l * 64, ab + (2 * l) * 128, u,
                             stats + (2 * l + 1) * 128, NN);
        bnfin_kernel<<<1, 64>>>(stats + (2 * l + 1) * 128, gout + l * 64, beout + l * 64,
                                ab + (2 * l + 1) * 128);
        hpool_kernel<<<HPB, 256>>>(u, ab + (2 * l + 1) * 128, batch,
                                   h, pooled + (l + 1) * GG * DD, NN);
    }

    score_kernel<<<(GG * CC + 255) / 256, 256>>>(pooled, Wp, bp, (float*)d_out);
}

// round 3
// speedup vs baseline: 1.6656x; 1.1571x over previous
#include <cuda_runtime.h>
#include <cuda_bf16.h>

// Problem constants (fixed by the dataset)
constexpr int NN = 100000;   // nodes
constexpr int EE = 1600000;  // edges
constexpr int DD = 64;       // feature dim
constexpr int GG = 512;      // graphs
constexpr int CC = 10;       // classes
constexpr int LL = 5;        // layers (4 conv layers)
constexpr float BN_EPS = 1e-5f;
constexpr int SCAN_B = 1024;
constexpr int NBLK = (NN + SCAN_B - 1) / SCAN_B;   // 98

// Scratch (device globals; no allocation allowed)
__device__ float g_z[NN * DD];
__device__ float g_t[NN * DD];
__device__ float g_u[NN * DD];
__device__ float g_pooled[LL * GG * DD];
__device__ float g_stats[8 * 128];  // per BN: [0..63]=colsum, [64..127]=colsumsq
__device__ int   g_rowptr[NN + 1];
__device__ int   g_cursor[NN];
__device__ int   g_csr[EE];
__device__ int   g_bsum[NBLK];

// ---------------------------------------------------------------------------
// helpers
// ---------------------------------------------------------------------------
__device__ __forceinline__ void red4(float* p, float4 v) {
    asm volatile("red.global.add.v4.f32 [%0], {%1,%2,%3,%4};"
                 :: "l"(p), "f"(v.x), "f"(v.y), "f"(v.z), "f"(v.w) : "memory");
}

__device__ __forceinline__ float2 f2fma(float2 a, float2 b, float2 c) {
    float2 d;
    asm("{\n\t"
        ".reg .b64 ra, rb, rc, rd;\n\t"
        "mov.b64 ra, {%2, %3};\n\t"
        "mov.b64 rb, {%4, %5};\n\t"
        "mov.b64 rc, {%6, %7};\n\t"
        "fma.rn.f32x2 rd, ra, rb, rc;\n\t"
        "mov.b64 {%0, %1}, rd;\n\t"
        "}"
        : "=f"(d.x), "=f"(d.y)
        : "f"(a.x), "f"(a.y), "f"(b.x), "f"(b.y), "f"(c.x), "f"(c.y));
    return d;
}

// ---------------------------------------------------------------------------
// zero accumulators + degree counters (reuse g_rowptr as count buffer)
// ---------------------------------------------------------------------------
__global__ void zerok(float* __restrict__ pooled, float* __restrict__ stats,
                      int* __restrict__ cnt) {
    int i = blockIdx.x * 256 + threadIdx.x;
    if (i < LL * GG * DD) pooled[i] = 0.f;
    if (i < 8 * 128) stats[i] = 0.f;
    if (i <= NN) cnt[i] = 0;
}

// ---------------------------------------------------------------------------
// CSR build
// ---------------------------------------------------------------------------
__global__ void __launch_bounds__(256) hist_kernel(const int* __restrict__ ei,
                                                   int* __restrict__ cnt) {
    int e = blockIdx.x * 256 + threadIdx.x;
    if (e < EE) atomicAdd(&cnt[ei[EE + e]], 1);
}

__global__ void __launch_bounds__(SCAN_B) scanA_kernel(int* __restrict__ rp,
                                                       int* __restrict__ bsum) {
    __shared__ int sm[SCAN_B];
    int gid = blockIdx.x * SCAN_B + threadIdx.x;
    int v = (gid < NN) ? rp[gid] : 0;
    sm[threadIdx.x] = v;
    __syncthreads();
    for (int off = 1; off < SCAN_B; off <<= 1) {
        int t = (threadIdx.x >= off) ? sm[threadIdx.x - off] : 0;
        __syncthreads();
        sm[threadIdx.x] += t;
        __syncthreads();
    }
    if (gid < NN) rp[gid] = sm[threadIdx.x] - v;   // exclusive
    if (threadIdx.x == SCAN_B - 1) bsum[blockIdx.x] = sm[SCAN_B - 1];
}

// scanC with inline cross-block prefix (replaces the serial scanB kernel)
__global__ void __launch_bounds__(SCAN_B) scanC_kernel(int* __restrict__ rp,
                                                       const int* __restrict__ bsum,
                                                       int* __restrict__ cursor) {
    __shared__ int sb[128];
    int tid = threadIdx.x;
    if (tid < 128) sb[tid] = (tid < (int)blockIdx.x && tid < NBLK) ? bsum[tid] : 0;
    __syncthreads();
#pragma unroll
    for (int s = 64; s > 0; s >>= 1) {
        if (tid < s) sb[tid] += sb[tid + s];
        __syncthreads();
    }
    int off = sb[0];
    int gid = blockIdx.x * SCAN_B + tid;
    if (gid < NN) {
        int v = rp[gid] + off;
        rp[gid] = v;
        cursor[gid] = v;
    }
    if (gid == 0) rp[NN] = EE;
}

__global__ void __launch_bounds__(256) fill_kernel(const int* __restrict__ ei,
                                                   int* __restrict__ cursor,
                                                   int* __restrict__ csr) {
    int e = blockIdx.x * 256 + threadIdx.x;
    if (e < EE) {
        int d = ei[EE + e];
        int pos = atomicAdd(&cursor[d], 1);
        csr[pos] = ei[e];
    }
}

// ---------------------------------------------------------------------------
// gather: z[n] = (1+eps)*T(src[n]) + sum_{nbr} T(src[nbr])
// where T = relu(alpha*x+beta) (BN from stats) if st != null, else identity.
// Also pools T(src[n]) into pooled_l (this IS hidden_rep[l]).
// 16 threads per node; ab computed per-block into smem (one rsqrt per column).
// Grid is exact (NN*16 threads), so the barrier is safe.
// ---------------------------------------------------------------------------
__global__ void __launch_bounds__(256) gather_kernel(
    const float* __restrict__ src,
    const float* __restrict__ st, const float* __restrict__ gamma,
    const float* __restrict__ beta,
    const int* __restrict__ rowptr, const int* __restrict__ csr,
    const float* __restrict__ eps_l, const int* __restrict__ batch,
    float* __restrict__ pooled_l, float* __restrict__ z)
{
    __shared__ float ab_s[128];
    const int tid = threadIdx.x;
    if (st) {
        if (tid < 64) {
            const float inv_n = 1.0f / (float)NN;
            float m = st[tid] * inv_n;
            float v = st[64 + tid] * inv_n - m * m;
            float rs = rsqrtf(v + BN_EPS);
            float al = gamma[tid] * rs;
            ab_s[tid] = al;
            ab_s[64 + tid] = beta[tid] - al * m;
        }
        __syncthreads();
    }
    int idx = blockIdx.x * 256 + tid;
    int n = idx >> 4;
    int j = (idx & 15) << 2;
    int s = rowptr[n];
    int e = rowptr[n + 1];
    float em1 = 1.0f + *eps_l;
    int g = batch[n];
    float4 acc;

    if (st) {
        float a0 = ab_s[j + 0], a1 = ab_s[j + 1], a2 = ab_s[j + 2], a3 = ab_s[j + 3];
        float b0 = ab_s[64 + j + 0], b1 = ab_s[64 + j + 1],
              b2 = ab_s[64 + j + 2], b3 = ab_s[64 + j + 3];
        float4 hv = *(const float4*)(src + n * DD + j);
        hv.x = fmaxf(fmaf(a0, hv.x, b0), 0.f);
        hv.y = fmaxf(fmaf(a1, hv.y, b1), 0.f);
        hv.z = fmaxf(fmaf(a2, hv.z, b2), 0.f);
        hv.w = fmaxf(fmaf(a3, hv.w, b3), 0.f);
        red4(pooled_l + g * DD + j, hv);
        acc = make_float4(em1 * hv.x, em1 * hv.y, em1 * hv.z, em1 * hv.w);
        int i = s;
        for (; i + 2 <= e; i += 2) {
            int s0 = csr[i], s1 = csr[i + 1];
            float4 v0 = *(const float4*)(src + s0 * DD + j);
            float4 v1 = *(const float4*)(src + s1 * DD + j);
            acc.x += fmaxf(fmaf(a0, v0.x, b0), 0.f) + fmaxf(fmaf(a0, v1.x, b0), 0.f);
            acc.y += fmaxf(fmaf(a1, v0.y, b1), 0.f) + fmaxf(fmaf(a1, v1.y, b1), 0.f);
            acc.z += fmaxf(fmaf(a2, v0.z, b2), 0.f) + fmaxf(fmaf(a2, v1.z, b2), 0.f);
            acc.w += fmaxf(fmaf(a3, v0.w, b3), 0.f) + fmaxf(fmaf(a3, v1.w, b3), 0.f);
        }
        for (; i < e; i++) {
            int sv = csr[i];
            float4 v = *(const float4*)(src + sv * DD + j);
            acc.x += fmaxf(fmaf(a0, v.x, b0), 0.f);
            acc.y += fmaxf(fmaf(a1, v.y, b1), 0.f);
            acc.z += fmaxf(fmaf(a2, v.z, b2), 0.f);
            acc.w += fmaxf(fmaf(a3, v.w, b3), 0.f);
        }
    } else {
        float4 hv = *(const float4*)(src + n * DD + j);
        red4(pooled_l + g * DD + j, hv);
        acc = make_float4(em1 * hv.x, em1 * hv.y, em1 * hv.z, em1 * hv.w);
        int i = s;
        for (; i + 4 <= e; i += 4) {
            int s0 = csr[i], s1 = csr[i + 1], s2 = csr[i + 2], s3 = csr[i + 3];
            float4 v0 = *(const float4*)(src + s0 * DD + j);
            float4 v1 = *(const float4*)(src + s1 * DD + j);
            float4 v2 = *(const float4*)(src + s2 * DD + j);
            float4 v3 = *(const float4*)(src + s3 * DD + j);
            acc.x += v0.x + v1.x + v2.x + v3.x;
            acc.y += v0.y + v1.y + v2.y + v3.y;
            acc.z += v0.z + v1.z + v2.z + v3.z;
            acc.w += v0.w + v1.w + v2.w + v3.w;
        }
        for (; i < e; i++) {
            int sv = csr[i];
            float4 v = *(const float4*)(src + sv * DD + j);
            acc.x += v.x; acc.y += v.y; acc.z += v.z; acc.w += v.w;
        }
    }
    *(float4*)(z + n * DD + j) = acc;
}

// ---------------------------------------------------------------------------
// final-layer pool: pooled += relu(bn(src)) ; ab from stats per block
// ---------------------------------------------------------------------------
__global__ void __launch_bounds__(256) hpool_kernel(
    const float* __restrict__ src, const float* __restrict__ st,
    const float* __restrict__ gamma, const float* __restrict__ beta,
    const int* __restrict__ batch, float* __restrict__ pooled_l)
{
    __shared__ float ab_s[128];
    const int tid = threadIdx.x;
    if (tid < 64) {
        const float inv_n = 1.0f / (float)NN;
        float m = st[tid] * inv_n;
        float v = st[64 + tid] * inv_n - m * m;
        float rs = rsqrtf(v + BN_EPS);
        float al = gamma[tid] * rs;
        ab_s[tid] = al;
        ab_s[64 + tid] = beta[tid] - al * m;
    }
    __syncthreads();
    int idx = blockIdx.x * 256 + tid;
    int n = idx >> 4;
    int j = (idx & 15) << 2;
    float4 v = *(const float4*)(src + n * DD + j);
    v.x = fmaxf(fmaf(ab_s[j + 0], v.x, ab_s[64 + j + 0]), 0.f);
    v.y = fmaxf(fmaf(ab_s[j + 1], v.y, ab_s[64 + j + 1]), 0.f);
    v.z = fmaxf(fmaf(ab_s[j + 2], v.z, ab_s[64 + j + 2]), 0.f);
    v.w = fmaxf(fmaf(ab_s[j + 3], v.w, ab_s[64 + j + 3]), 0.f);
    red4(pooled_l + batch[n] * DD + j, v);
}

// ---------------------------------------------------------------------------
// GEMM: Out[N,64] = T(A)[N,64] @ W[64,64] + bias, fused column stats.
// T(a)[.,k] = relu(alpha[k]*a+beta[k]) (from st_in) if st_in != null.
// Block: 256 threads, 128 rows. Thread: 4 rows x 8 cols. Dynamic smem.
// ---------------------------------------------------------------------------
constexpr int GEMM_SMEM = (4096 + 128 * 68 + 128 + 128) * 4;  // 52224 B

__global__ void __launch_bounds__(256) gemm64(
    const float* __restrict__ A, const float* __restrict__ W,
    const float* __restrict__ bias,
    const float* __restrict__ st_in, const float* __restrict__ gamma,
    const float* __restrict__ beta,
    float* __restrict__ Out, float* __restrict__ st_out, int nrows)
{
    extern __shared__ float smem[];
    float* Ws = smem;                               // [64][64]
    float (*As)[68] = (float(*)[68])(smem + 4096);  // [128][68]
    float* ab_s = smem + 4096 + 128 * 68;           // [128]
    float* sst  = ab_s + 128;                       // [128]

    const int tid = threadIdx.x;
    const int row0 = blockIdx.x * 128;

    if (tid < 128) sst[tid] = 0.f;
    if (st_in && tid < 64) {
        const float inv_n = 1.0f / (float)NN;
        float m = st_in[tid] * inv_n;
        float v = st_in[64 + tid] * inv_n - m * m;
        float rs = rsqrtf(v + BN_EPS);
        float al = gamma[tid] * rs;
        ab_s[tid] = al;
        ab_s[64 + tid] = beta[tid] - al * m;
    }
    // load W (64x64)
    for (int i = tid; i < 1024; i += 256) {
        int k = i >> 4, c = (i & 15) << 2;
        *(float4*)&Ws[k * 64 + c] = *(const float4*)(W + k * 64 + c);
    }
    __syncthreads();   // ab_s ready before A staging

    // load A tile (128 rows) with optional BN+ReLU transform
    for (int i = tid; i < 2048; i += 256) {
        int r = i >> 4, c = (i & 15) << 2;
        int gr = row0 + r;
        float4 a = make_float4(0.f, 0.f, 0.f, 0.f);
        if (gr < nrows) a = *(const float4*)(A + gr * 64 + c);
        if (st_in) {
            a.x = fmaxf(fmaf(ab_s[c + 0], a.x, ab_s[64 + c + 0]), 0.f);
            a.y = fmaxf(fmaf(ab_s[c + 1], a.y, ab_s[64 + c + 1]), 0.f);
            a.z = fmaxf(fmaf(ab_s[c + 2], a.z, ab_s[64 + c + 2]), 0.f);
            a.w = fmaxf(fmaf(ab_s[c + 3], a.w, ab_s[64 + c + 3]), 0.f);
        }
        *(float4*)&As[r][c] = a;
    }
    __syncthreads();

    const int tc = tid & 7;     // col group: cols 4tc..4tc+3 and 32+4tc..
    const int rg = tid >> 3;    // 0..31
    const int r0 = 4 * rg;

    float2 acc[4][4];
#pragma unroll
    for (int i = 0; i < 4; i++)
#pragma unroll
        for (int jq = 0; jq < 4; jq++) acc[i][jq] = make_float2(0.f, 0.f);

#pragma unroll
    for (int kc = 0; kc < 64; kc += 8) {
        float a[4][8];
#pragma unroll
        for (int rr = 0; rr < 4; rr++) {
            float4 t0 = *(const float4*)&As[r0 + rr][kc];
            float4 t1 = *(const float4*)&As[r0 + rr][kc + 4];
            a[rr][0] = t0.x; a[rr][1] = t0.y; a[rr][2] = t0.z; a[rr][3] = t0.w;
            a[rr][4] = t1.x; a[rr][5] = t1.y; a[rr][6] = t1.z; a[rr][7] = t1.w;
        }
#pragma unroll
        for (int kk = 0; kk < 8; kk++) {
            const float* wr = &Ws[(kc + kk) * 64 + 4 * tc];
            float4 wl = *(const float4*)wr;
            float4 wh = *(const float4*)(wr + 32);
            float2 wl01 = make_float2(wl.x, wl.y), wl23 = make_float2(wl.z, wl.w);
            float2 wh01 = make_float2(wh.x, wh.y), wh23 = make_float2(wh.z, wh.w);
#pragma unroll
            for (int rr = 0; rr < 4; rr++) {
                float2 Av = make_float2(a[rr][kk], a[rr][kk]);
                acc[rr][0] = f2fma(Av, wl01, acc[rr][0]);
                acc[rr][1] = f2fma(Av, wl23, acc[rr][1]);
                acc[rr][2] = f2fma(Av, wh01, acc[rr][2]);
                acc[rr][3] = f2fma(Av, wh23, acc[rr][3]);
            }
        }
    }

    float4 blo = *(const float4*)(bias + 4 * tc);
    float4 bhi = *(const float4*)(bias + 32 + 4 * tc);
    float4 slo = make_float4(0.f, 0.f, 0.f, 0.f), shi = slo, qlo = slo, qhi = slo;
#pragma unroll
    for (int i = 0; i < 4; i++) {
        int gr = row0 + r0 + i;
        if (gr < nrows) {
            float4 o0 = make_float4(acc[i][0].x + blo.x, acc[i][0].y + blo.y,
                                    acc[i][1].x + blo.z, acc[i][1].y + blo.w);
            float4 o1 = make_float4(acc[i][2].x + bhi.x, acc[i][2].y + bhi.y,
                                    acc[i][3].x + bhi.z, acc[i][3].y + bhi.w);
            *(float4*)(Out + gr * 64 + 4 * tc) = o0;
            *(float4*)(Out + gr * 64 + 32 + 4 * tc) = o1;
            slo.x += o0.x; slo.y += o0.y; slo.z += o0.z; slo.w += o0.w;
            shi.x += o1.x; shi.y += o1.y; shi.z += o1.z; shi.w += o1.w;
            qlo.x += o0.x * o0.x; qlo.y += o0.y * o0.y; qlo.z += o0.z * o0.z; qlo.w += o0.w * o0.w;
            qhi.x += o1.x * o1.x; qhi.y += o1.y * o1.y; qhi.z += o1.z * o1.z; qhi.w += o1.w * o1.w;
        }
    }
    // lanes sharing tc within a warp differ in bits 3,4
#pragma unroll
    for (int m = 8; m <= 16; m <<= 1) {
        slo.x += __shfl_xor_sync(~0u, slo.x, m); slo.y += __shfl_xor_sync(~0u, slo.y, m);
        slo.z += __shfl_xor_sync(~0u, slo.z, m); slo.w += __shfl_xor_sync(~0u, slo.w, m);
        shi.x += __shfl_xor_sync(~0u, shi.x, m); shi.y += __shfl_xor_sync(~0u, shi.y, m);
        shi.z += __shfl_xor_sync(~0u, shi.z, m); shi.w += __shfl_xor_sync(~0u, shi.w, m);
        qlo.x += __shfl_xor_sync(~0u, qlo.x, m); qlo.y += __shfl_xor_sync(~0u, qlo.y, m);
        qlo.z += __shfl_xor_sync(~0u, qlo.z, m); qlo.w += __shfl_xor_sync(~0u, qlo.w, m);
        qhi.x += __shfl_xor_sync(~0u, qhi.x, m); qhi.y += __shfl_xor_sync(~0u, qhi.y, m);
        qhi.z += __shfl_xor_sync(~0u, qhi.z, m); qhi.w += __shfl_xor_sync(~0u, qhi.w, m);
    }
    if ((tid & 24) == 0) {
        int c = 4 * tc;
        atomicAdd(&sst[c + 0], slo.x); atomicAdd(&sst[c + 1], slo.y);
        atomicAdd(&sst[c + 2], slo.z); atomicAdd(&sst[c + 3], slo.w);
        atomicAdd(&sst[32 + c + 0], shi.x); atomicAdd(&sst[32 + c + 1], shi.y);
        atomicAdd(&sst[32 + c + 2], shi.z); atomicAdd(&sst[32 + c + 3], shi.w);
        atomicAdd(&sst[64 + c + 0], qlo.x); atomicAdd(&sst[64 + c + 1], qlo.y);
        atomicAdd(&sst[64 + c + 2], qlo.z); atomicAdd(&sst[64 + c + 3], qlo.w);
        atomicAdd(&sst[96 + c + 0], qhi.x); atomicAdd(&sst[96 + c + 1], qhi.y);
        atomicAdd(&sst[96 + c + 2], qhi.z); atomicAdd(&sst[96 + c + 3], qhi.w);
    }
    __syncthreads();
    if (tid < 128) atomicAdd(&st_out[tid], sst[tid]);
}

// ---------------------------------------------------------------------------
// final readout
// ---------------------------------------------------------------------------
__global__ void score_kernel(const float* __restrict__ pooled,
                             const float* __restrict__ Wp,
                             const float* __restrict__ bp,
                             float* __restrict__ out)
{
    int t = blockIdx.x * 256 + threadIdx.x;
    if (t >= GG * CC) return;
    int g = t / CC, c = t % CC;
    float acc = 0.f;
#pragma unroll
    for (int l = 0; l < LL; l++) {
        acc += bp[l * CC + c];
        const float* pl = pooled + (l * GG + g) * DD;
        const float* wl = Wp + l * DD * CC + c;
        float s = 0.f;
#pragma unroll
        for (int d = 0; d < DD; d++) s += pl[d] * wl[d * CC];
        acc += s;
    }
    out[g * CC + c] = acc;
}

// ---------------------------------------------------------------------------
extern "C" void kernel_launch(void* const* d_in, const int* in_sizes, int n_in,
                              void* d_out, int out_size)
{
    (void)in_sizes; (void)n_in; (void)out_size;
    const float* x     = (const float*)d_in[0];
    const int*   ei    = (const int*)d_in[1];
    const int*   batch = (const int*)d_in[2];
    const float* eps   = (const float*)d_in[3];
    const float* W1    = (const float*)d_in[4];
    const float* b1    = (const float*)d_in[5];
    const float* g1    = (const float*)d_in[6];
    const float* be1   = (const float*)d_in[7];
    const float* W2    = (const float*)d_in[8];
    const float* b2    = (const float*)d_in[9];
    const float* gout  = (const float*)d_in[10];
    const float* beout = (const float*)d_in[11];
    const float* Wp    = (const float*)d_in[12];
    const float* bp    = (const float*)d_in[13];

    float *z, *t, *u, *pooled, *stats;
    int *rowptr, *cursor, *csr, *bsum;
    cudaGetSymbolAddress((void**)&z, g_z);
    cudaGetSymbolAddress((void**)&t, g_t);
    cudaGetSymbolAddress((void**)&u, g_u);
    cudaGetSymbolAddress((void**)&pooled, g_pooled);
    cudaGetSymbolAddress((void**)&stats, g_stats);
    cudaGetSymbolAddress((void**)&rowptr, g_rowptr);
    cudaGetSymbolAddress((void**)&cursor, g_cursor);
    cudaGetSymbolAddress((void**)&csr, g_csr);
    cudaGetSymbolAddress((void**)&bsum, g_bsum);

    static bool attr_set = false;
    if (!attr_set) {
        cudaFuncSetAttribute(gemm64, cudaFuncAttributeMaxDynamicSharedMemorySize,
                             GEMM_SMEM);
        attr_set = true;
    }

    const int HPB = (NN * 16) / 256;          // 6250 (exact)
    const int EB  = (EE + 255) / 256;         // 6250
    const int GMB = (NN + 127) / 128;         // 782

    zerok<<<(LL * GG * DD + 255) / 256, 256>>>(pooled, stats, rowptr);

    // CSR build
    hist_kernel<<<EB, 256>>>(ei, rowptr);
    scanA_kernel<<<NBLK, SCAN_B>>>(rowptr, bsum);
    scanC_kernel<<<NBLK, SCAN_B>>>(rowptr, bsum, cursor);
    fill_kernel<<<EB, 256>>>(ei, cursor, csr);

    for (int l = 0; l < LL - 1; l++) {
        if (l == 0) {
            gather_kernel<<<HPB, 256>>>(x, nullptr, nullptr, nullptr,
                                        rowptr, csr, eps, batch, pooled, z);
        } else {
            gather_kernel<<<HPB, 256>>>(u, stats + (2 * (l - 1) + 1) * 128,
                                        gout + (l - 1) * 64, beout + (l - 1) * 64,
                                        rowptr, csr, eps + l, batch,
                                        pooled + l * GG * DD, z);
        }
        gemm64<<<GMB, 256, GEMM_SMEM>>>(z, W1 + l * 4096, b1 + l * 64,
                                        nullptr, nullptr, nullptr,
                                        t, stats + (2 * l) * 128, NN);
        gemm64<<<GMB, 256, GEMM_SMEM>>>(t, W2 + l * 4096, b2 + l * 64,
                                        stats + (2 * l) * 128, g1 + l * 64, be1 + l * 64,
                                        u, stats + (2 * l + 1) * 128, NN);
    }
    hpool_kernel<<<HPB, 256>>>(u, stats + 7 * 128, gout + 3 * 64, beout + 3 * 64,
                               batch, pooled + 4 * GG * DD);

    score_kernel<<<(GG * CC + 255) / 256, 256>>>(pooled, Wp, bp, (float*)d_out);
}